// round 1
// baseline (speedup 1.0000x reference)
#include <cuda_runtime.h>
#include <math.h>

#define EE 512
#define LDIM 64
#define ADIM 64
#define HH 8
#define BB 4
#define SS 2048
#define NROW (BB*SS)            // 8192
#define FF 2048                 // 2LH + 2AH
#define LH 512
#define OFF_U 0
#define OFF_V 512
#define OFF_Q 1024
#define OFF_K 1536

// Scratch (allocation-free rule: __device__ globals)
__device__ float g_normed[(size_t)NROW*EE];   // 16.8 MB
__device__ float g_proj[(size_t)NROW*FF];     // 67 MB
__device__ float g_attn[(size_t)NROW*LH];     // 16.8 MB

// ---------------- block reduction (256 threads) ----------------
__device__ __forceinline__ float2 block_reduce_sum2(float sum, float sq) {
    __shared__ float sh[16];
    int lane = threadIdx.x & 31, w = threadIdx.x >> 5;
#pragma unroll
    for (int o = 16; o > 0; o >>= 1) {
        sum += __shfl_xor_sync(0xffffffffu, sum, o);
        sq  += __shfl_xor_sync(0xffffffffu, sq, o);
    }
    if (lane == 0) { sh[w] = sum; sh[8 + w] = sq; }
    __syncthreads();
    float s = 0.f, q = 0.f;
#pragma unroll
    for (int i = 0; i < 8; i++) { s += sh[i]; q += sh[8 + i]; }
    return make_float2(s, q);
}

// ---------------- 1) input LayerNorm ----------------
__global__ __launch_bounds__(256) void ln_in_kernel(const float* __restrict__ x,
                                                    const float* __restrict__ g,
                                                    const float* __restrict__ be) {
    const int row = blockIdx.x, t = threadIdx.x;
    const float* xr = x + (size_t)row * EE;
    float v0 = xr[t], v1 = xr[t + 256];
    float2 r = block_reduce_sum2(v0 + v1, v0 * v0 + v1 * v1);
    float mu = r.x * (1.f / 512.f);
    float var = r.y * (1.f / 512.f) - mu * mu;
    float rs = rsqrtf(var + 1e-6f);
    float* orow = g_normed + (size_t)row * EE;
    orow[t]       = (v0 - mu) * rs * g[t]       + be[t];
    orow[t + 256] = (v1 - mu) * rs * g[t + 256] + be[t + 256];
}

// ---------------- 2) projection GEMM: g_proj = g_normed @ W ----------------
// 128x64 tile, BK=16, 256 threads, 8x4 micro-tile
__global__ __launch_bounds__(256) void gemm_proj_kernel(const float* __restrict__ W) {
    __shared__ float As[16][129];
    __shared__ float Bs[16][64];
    const int t = threadIdx.x;
    const int tx = t & 15, ty = t >> 4;
    const int bm = blockIdx.y * 128, bn = blockIdx.x * 64;
    float acc[8][4] = {};
    for (int k0 = 0; k0 < EE; k0 += 16) {
#pragma unroll
        for (int i = 0; i < 8; i++) {
            int idx = t + i * 256;            // 0..2047
            int r = idx >> 4, kk = idx & 15;
            As[kk][r] = g_normed[(size_t)(bm + r) * EE + k0 + kk];
        }
#pragma unroll
        for (int i = 0; i < 4; i++) {
            int idx = t + i * 256;            // 0..1023
            int kk = idx >> 6, n = idx & 63;
            Bs[kk][n] = W[(size_t)(k0 + kk) * FF + bn + n];
        }
        __syncthreads();
#pragma unroll
        for (int kk = 0; kk < 16; kk++) {
            float a[8], bb[4];
#pragma unroll
            for (int i = 0; i < 8; i++) a[i] = As[kk][ty * 8 + i];
#pragma unroll
            for (int j = 0; j < 4; j++) bb[j] = Bs[kk][tx * 4 + j];
#pragma unroll
            for (int i = 0; i < 8; i++)
#pragma unroll
                for (int j = 0; j < 4; j++) acc[i][j] += a[i] * bb[j];
        }
        __syncthreads();
    }
#pragma unroll
    for (int i = 0; i < 8; i++)
#pragma unroll
        for (int j = 0; j < 4; j++)
            g_proj[(size_t)(bm + ty * 8 + i) * FF + bn + tx * 4 + j] = acc[i][j];
}

// ---------------- 3) causal silu-attention ----------------
// grid: (ntile=32, b*H=32); block 256. Dynamic smem:
// qs[64][65] (d-major), ks[64][65] (d-major), ps[64][65] (m-major), vs[64][64]
#define ATTN_SMEM ((3 * 64 * 65 + 64 * 64) * 4)
__global__ __launch_bounds__(256) void attn_kernel(const float* __restrict__ mask) {
    extern __shared__ float sm[];
    float (*qs)[65] = reinterpret_cast<float(*)[65]>(sm);
    float (*ks)[65] = reinterpret_cast<float(*)[65]>(sm + 64 * 65);
    float (*ps)[65] = reinterpret_cast<float(*)[65]>(sm + 2 * 64 * 65);
    float (*vs)[64] = reinterpret_cast<float(*)[64]>(sm + 3 * 64 * 65);

    const int t = threadIdx.x, tx = t & 15, ty = t >> 4;
    const int ntile = blockIdx.x, bh = blockIdx.y;
    const int b = bh >> 3, h = bh & 7;
    const int n0 = ntile << 6;
    const size_t base = (size_t)b * SS;

    // load q tile transposed: qs[d][n_local]
#pragma unroll
    for (int i = 0; i < 16; i++) {
        int idx = t + (i << 8); int r = idx >> 6, d = idx & 63;
        qs[d][r] = g_proj[(base + n0 + r) * FF + OFF_Q + (h << 6) + d];
    }

    float o[4][4] = {};
    for (int mt = 0; mt <= ntile; ++mt) {
        const int m0 = mt << 6;
        __syncthreads();   // protect smem vs prior iter readers; also fences q load (iter 0)
#pragma unroll
        for (int i = 0; i < 16; i++) {
            int idx = t + (i << 8); int r = idx >> 6, d = idx & 63;
            const float* rowp = g_proj + (base + m0 + r) * FF;
            ks[d][r] = rowp[OFF_K + (h << 6) + d];
            vs[r][d] = rowp[OFF_V + (h << 6) + d];
        }
        __syncthreads();
        // S = q @ k^T  (64x64)
        float s[4][4] = {};
#pragma unroll
        for (int d = 0; d < 64; ++d) {
            float a[4], kb[4];
#pragma unroll
            for (int i = 0; i < 4; i++) a[i] = qs[d][ty * 4 + i];
#pragma unroll
            for (int j = 0; j < 4; j++) kb[j] = ks[d][tx * 4 + j];
#pragma unroll
            for (int i = 0; i < 4; i++)
#pragma unroll
                for (int j = 0; j < 4; j++) s[i][j] += a[i] * kb[j];
        }
        // silu * mask, store transposed (m-major) for the PV GEMM
#pragma unroll
        for (int i = 0; i < 4; i++) {
            const int gn = n0 + ty * 4 + i;
            const float* mrow = mask + (size_t)gn * SS + m0;
#pragma unroll
            for (int j = 0; j < 4; j++) {
                float x = s[i][j];
                float sg = 1.0f / (1.0f + expf(-x));
                ps[tx * 4 + j][ty * 4 + i] = x * sg * mrow[tx * 4 + j];
            }
        }
        __syncthreads();
        // O += P @ V
#pragma unroll
        for (int m = 0; m < 64; ++m) {
            float p[4], vv[4];
#pragma unroll
            for (int i = 0; i < 4; i++) p[i] = ps[m][ty * 4 + i];
#pragma unroll
            for (int j = 0; j < 4; j++) vv[j] = vs[m][tx * 4 + j];
#pragma unroll
            for (int i = 0; i < 4; i++)
#pragma unroll
                for (int j = 0; j < 4; j++) o[i][j] += p[i] * vv[j];
        }
    }
#pragma unroll
    for (int i = 0; i < 4; i++)
#pragma unroll
        for (int j = 0; j < 4; j++)
            g_attn[(base + n0 + ty * 4 + i) * LH + (h << 6) + tx * 4 + j] = o[i][j];
}

// ---------------- 4) output LN * u + residual ----------------
__global__ __launch_bounds__(256) void out_kernel(const float* __restrict__ ue,
                                                  const float* __restrict__ g,
                                                  const float* __restrict__ be,
                                                  float* __restrict__ out) {
    const int row = blockIdx.x, t = threadIdx.x;
    const float* ar = g_attn + (size_t)row * LH;
    float a0 = ar[t], a1 = ar[t + 256];
    float2 r = block_reduce_sum2(a0 + a1, a0 * a0 + a1 * a1);
    float mu = r.x * (1.f / 512.f);
    float var = r.y * (1.f / 512.f) - mu * mu;
    float rs = rsqrtf(var + 1e-6f);
    const float* ur  = g_proj + (size_t)row * FF + OFF_U;
    const float* uer = ue + (size_t)row * EE;
    float* orow = out + (size_t)row * EE;
    orow[t]       = uer[t]       + ((a0 - mu) * rs * g[t]       + be[t])       * ur[t];
    orow[t + 256] = uer[t + 256] + ((a1 - mu) * rs * g[t + 256] + be[t + 256]) * ur[t + 256];
}

extern "C" void kernel_launch(void* const* d_in, const int* in_sizes, int n_in,
                              void* d_out, int out_size) {
    (void)in_sizes; (void)n_in; (void)out_size;
    const float* ue   = (const float*)d_in[0];
    const float* mask = (const float*)d_in[1];
    const float* uvqk = (const float*)d_in[2];
    const float* ing  = (const float*)d_in[3];
    const float* inb  = (const float*)d_in[4];
    const float* outg = (const float*)d_in[5];
    const float* outb = (const float*)d_in[6];
    float* out = (float*)d_out;

    cudaFuncSetAttribute(attn_kernel, cudaFuncAttributeMaxDynamicSharedMemorySize, ATTN_SMEM);

    ln_in_kernel<<<NROW, 256>>>(ue, ing, inb);
    gemm_proj_kernel<<<dim3(FF / 64, NROW / 128), 256>>>(uvqk);
    attn_kernel<<<dim3(SS / 64, BB * HH), 256, ATTN_SMEM>>>(mask);
    out_kernel<<<NROW, 256>>>(ue, outg, outb, out);
}

// round 2
// speedup vs baseline: 2.7863x; 2.7863x over previous
#include <cuda_runtime.h>
#include <math.h>

#define EE 512
#define HH 8
#define BB 4
#define SS 2048
#define NROW (BB*SS)            // 8192
#define FF 2048                 // 2LH + 2AH
#define LH 512
#define OFF_U 0
#define OFF_V 512
#define OFF_Q 1024
#define OFF_K 1536

// Scratch (allocation-free rule: __device__ globals)
__device__ float g_normed[(size_t)NROW*EE];   // 16.8 MB
__device__ float g_proj[(size_t)NROW*FF];     // 67 MB
__device__ float g_attn[(size_t)NROW*LH];     // 16.8 MB

// ---------------- helpers ----------------
__device__ __forceinline__ float tf(float x) {
    unsigned r;
    asm("cvt.rna.tf32.f32 %0, %1;" : "=r"(r) : "f"(x));
    return __uint_as_float(r);
}

__device__ __forceinline__ void mma_tf32(float* d, const unsigned* a, const unsigned* b) {
    asm volatile(
        "mma.sync.aligned.m16n8k8.row.col.f32.tf32.tf32.f32 "
        "{%0,%1,%2,%3}, {%4,%5,%6,%7}, {%8,%9}, {%0,%1,%2,%3};\n"
        : "+f"(d[0]), "+f"(d[1]), "+f"(d[2]), "+f"(d[3])
        : "r"(a[0]), "r"(a[1]), "r"(a[2]), "r"(a[3]), "r"(b[0]), "r"(b[1]));
}

__device__ __forceinline__ float2 block_reduce_sum2(float sum, float sq) {
    __shared__ float sh[16];
    int lane = threadIdx.x & 31, w = threadIdx.x >> 5;
#pragma unroll
    for (int o = 16; o > 0; o >>= 1) {
        sum += __shfl_xor_sync(0xffffffffu, sum, o);
        sq  += __shfl_xor_sync(0xffffffffu, sq, o);
    }
    if (lane == 0) { sh[w] = sum; sh[8 + w] = sq; }
    __syncthreads();
    float s = 0.f, q = 0.f;
#pragma unroll
    for (int i = 0; i < 8; i++) { s += sh[i]; q += sh[8 + i]; }
    return make_float2(s, q);
}

// ---------------- 1) input LayerNorm ----------------
__global__ __launch_bounds__(256) void ln_in_kernel(const float* __restrict__ x,
                                                    const float* __restrict__ g,
                                                    const float* __restrict__ be) {
    const int row = blockIdx.x, t = threadIdx.x;
    const float* xr = x + (size_t)row * EE;
    float v0 = xr[t], v1 = xr[t + 256];
    float2 r = block_reduce_sum2(v0 + v1, v0 * v0 + v1 * v1);
    float mu = r.x * (1.f / 512.f);
    float var = r.y * (1.f / 512.f) - mu * mu;
    float rs = rsqrtf(var + 1e-6f);
    float* orow = g_normed + (size_t)row * EE;
    orow[t]       = (v0 - mu) * rs * g[t]       + be[t];
    orow[t + 256] = (v1 - mu) * rs * g[t + 256] + be[t + 256];
}

// ---------------- 2) projection GEMM (tf32 tensor cores) ----------------
// 128x128 block tile, BK=32, 256 threads, 8 warps (2m x 4n), warp tile 64x32
__global__ __launch_bounds__(256) void gemm_proj_kernel(const float* __restrict__ W) {
    __shared__ float As[128][36];   // [m][k], stride 36 -> conflict-free frag reads
    __shared__ float Bs[32][132];   // [k][n]
    const int t = threadIdx.x;
    const int wid = t >> 5, lane = t & 31;
    const int gid = lane >> 2, tig = lane & 3;
    const int warp_m = wid & 1, warp_n = wid >> 1;
    const int m0 = warp_m * 64, n0 = warp_n * 32;
    const int bm = blockIdx.y * 128, bn = blockIdx.x * 128;

    const int a_kq = t & 7, a_m = t >> 3;     // A loader: 32f contiguous per 8 threads
    const int b_n4 = t & 31, b_k = t >> 5;    // B loader: 128f contiguous per warp

    float acc[4][4][4] = {};

    for (int k0 = 0; k0 < EE; k0 += 32) {
        __syncthreads();
#pragma unroll
        for (int i = 0; i < 4; i++) {
            const int m = a_m + i * 32;
            const float4 v = *(const float4*)&g_normed[(size_t)(bm + m) * EE + k0 + a_kq * 4];
            float* dst = &As[m][a_kq * 4];
            dst[0] = tf(v.x); dst[1] = tf(v.y); dst[2] = tf(v.z); dst[3] = tf(v.w);
        }
#pragma unroll
        for (int i = 0; i < 4; i++) {
            const int kk = b_k + i * 8;
            const float4 v = *(const float4*)&W[(size_t)(k0 + kk) * FF + bn + b_n4 * 4];
            float* dst = &Bs[kk][b_n4 * 4];
            dst[0] = tf(v.x); dst[1] = tf(v.y); dst[2] = tf(v.z); dst[3] = tf(v.w);
        }
        __syncthreads();
#pragma unroll
        for (int ks = 0; ks < 32; ks += 8) {
            unsigned af[4][4], bf[4][2];
#pragma unroll
            for (int mi = 0; mi < 4; mi++) {
                const int mr = m0 + mi * 16;
                af[mi][0] = __float_as_uint(As[mr + gid][ks + tig]);
                af[mi][1] = __float_as_uint(As[mr + gid + 8][ks + tig]);
                af[mi][2] = __float_as_uint(As[mr + gid][ks + tig + 4]);
                af[mi][3] = __float_as_uint(As[mr + gid + 8][ks + tig + 4]);
            }
#pragma unroll
            for (int ni = 0; ni < 4; ni++) {
                const int nc = n0 + ni * 8 + gid;
                bf[ni][0] = __float_as_uint(Bs[ks + tig][nc]);
                bf[ni][1] = __float_as_uint(Bs[ks + tig + 4][nc]);
            }
#pragma unroll
            for (int mi = 0; mi < 4; mi++)
#pragma unroll
                for (int ni = 0; ni < 4; ni++)
                    mma_tf32(acc[mi][ni], af[mi], bf[ni]);
        }
    }
#pragma unroll
    for (int mi = 0; mi < 4; mi++)
#pragma unroll
        for (int ni = 0; ni < 4; ni++) {
            const int r = bm + m0 + mi * 16 + gid;
            const int c = bn + n0 + ni * 8 + 2 * tig;
            *(float2*)&g_proj[(size_t)r * FF + c]       = make_float2(acc[mi][ni][0], acc[mi][ni][1]);
            *(float2*)&g_proj[(size_t)(r + 8) * FF + c] = make_float2(acc[mi][ni][2], acc[mi][ni][3]);
        }
}

// ---------------- 3) causal silu-attention (tf32 tensor cores) ----------------
// grid (32 ntiles, 32 b*h), 256 threads = 8 warps (2n x 4m)
#define ATTN_SMEM (4 * 64 * 68 * 4)
__global__ __launch_bounds__(256) void attn_kernel() {
    extern __shared__ float sm[];
    float (*qs)[68] = reinterpret_cast<float(*)[68]>(sm);               // [n][d]
    float (*ks)[68] = reinterpret_cast<float(*)[68]>(sm + 64 * 68);     // [m][d]
    float (*vs)[68] = reinterpret_cast<float(*)[68]>(sm + 2 * 64 * 68); // [m][d]
    float (*ps)[68] = reinterpret_cast<float(*)[68]>(sm + 3 * 64 * 68); // [n][m]

    const int t = threadIdx.x;
    const int wid = t >> 5, lane = t & 31;
    const int gid = lane >> 2, tig = lane & 3;
    const int warp_n = wid >> 2;       // 0..1 : query-row half (32 rows)
    const int warp_m = wid & 3;        // 0..3 : key/col quarter (16)
    const int n0 = warp_n * 32, m0w = warp_m * 16;

    const int ntile = blockIdx.x, bh = blockIdx.y;
    const int b = bh >> 3, h = bh & 7;
    const int nbase = ntile << 6;
    const size_t base = (size_t)b * SS;
    const int hd = h << 6;

    const int q_d4 = t & 15, q_r = t >> 4;   // loader: 64f contiguous per 16 threads

    // load Q tile (tf32-converted)
#pragma unroll
    for (int i = 0; i < 4; i++) {
        const int row = q_r + i * 16;
        const float4 v = *(const float4*)&g_proj[(base + nbase + row) * FF + OFF_Q + hd + q_d4 * 4];
        float* dst = &qs[row][q_d4 * 4];
        dst[0] = tf(v.x); dst[1] = tf(v.y); dst[2] = tf(v.z); dst[3] = tf(v.w);
    }

    float o[2][2][4] = {};

    for (int mt = 0; mt <= ntile; ++mt) {
        const int m0b = mt << 6;
        __syncthreads();
#pragma unroll
        for (int i = 0; i < 4; i++) {
            const int row = q_r + i * 16;
            const float* rowp = &g_proj[(base + m0b + row) * FF + hd + q_d4 * 4];
            const float4 kv = *(const float4*)(rowp + OFF_K);
            const float4 vv = *(const float4*)(rowp + OFF_V);
            float* dk = &ks[row][q_d4 * 4];
            dk[0] = tf(kv.x); dk[1] = tf(kv.y); dk[2] = tf(kv.z); dk[3] = tf(kv.w);
            float* dv = &vs[row][q_d4 * 4];
            dv[0] = tf(vv.x); dv[1] = tf(vv.y); dv[2] = tf(vv.z); dv[3] = tf(vv.w);
        }
        __syncthreads();

        // S = Q @ K^T  (warp computes 32n x 16m)
        float s[2][2][4] = {};
#pragma unroll
        for (int ks8 = 0; ks8 < 8; ks8++) {
            const int d0 = ks8 * 8;
            unsigned aq[2][4], bk[2][2];
#pragma unroll
            for (int ni = 0; ni < 2; ni++) {
                const int r = n0 + ni * 16;
                aq[ni][0] = __float_as_uint(qs[r + gid][d0 + tig]);
                aq[ni][1] = __float_as_uint(qs[r + gid + 8][d0 + tig]);
                aq[ni][2] = __float_as_uint(qs[r + gid][d0 + tig + 4]);
                aq[ni][3] = __float_as_uint(qs[r + gid + 8][d0 + tig + 4]);
            }
#pragma unroll
            for (int mi = 0; mi < 2; mi++) {
                const int c = m0w + mi * 8 + gid;
                bk[mi][0] = __float_as_uint(ks[c][d0 + tig]);
                bk[mi][1] = __float_as_uint(ks[c][d0 + tig + 4]);
            }
#pragma unroll
            for (int ni = 0; ni < 2; ni++)
#pragma unroll
                for (int mi = 0; mi < 2; mi++)
                    mma_tf32(s[ni][mi], aq[ni], bk[mi]);
        }

        // silu * causal mask -> ps (tf32). diag tile masks ml > nl.
        const bool diag = (mt == ntile);
#pragma unroll
        for (int ni = 0; ni < 2; ni++)
#pragma unroll
            for (int mi = 0; mi < 2; mi++) {
                const int nl = n0 + ni * 16 + gid;
                const int ml = m0w + mi * 8 + 2 * tig;
#pragma unroll
                for (int cc = 0; cc < 4; cc++) {
                    const int rr = nl + (cc >> 1) * 8;
                    const int mm = ml + (cc & 1);
                    float x = s[ni][mi][cc];
                    float p = x / (1.0f + __expf(-x));
                    if (diag && mm > rr) p = 0.0f;
                    ps[rr][mm] = tf(p);
                }
            }
        __syncthreads();

        // O += P @ V  (warp computes 32n x 16d)
#pragma unroll
        for (int kk8 = 0; kk8 < 8; kk8++) {
            const int mk = kk8 * 8;
            unsigned ap[2][4], bv[2][2];
#pragma unroll
            for (int ni = 0; ni < 2; ni++) {
                const int r = n0 + ni * 16;
                ap[ni][0] = __float_as_uint(ps[r + gid][mk + tig]);
                ap[ni][1] = __float_as_uint(ps[r + gid + 8][mk + tig]);
                ap[ni][2] = __float_as_uint(ps[r + gid][mk + tig + 4]);
                ap[ni][3] = __float_as_uint(ps[r + gid + 8][mk + tig + 4]);
            }
#pragma unroll
            for (int di = 0; di < 2; di++) {
                const int c = m0w + di * 8 + gid;
                bv[di][0] = __float_as_uint(vs[mk + tig][c]);
                bv[di][1] = __float_as_uint(vs[mk + tig + 4][c]);
            }
#pragma unroll
            for (int ni = 0; ni < 2; ni++)
#pragma unroll
                for (int di = 0; di < 2; di++)
                    mma_tf32(o[ni][di], ap[ni], bv[di]);
        }
    }

#pragma unroll
    for (int ni = 0; ni < 2; ni++)
#pragma unroll
        for (int di = 0; di < 2; di++) {
            const size_t r = base + nbase + n0 + ni * 16 + gid;
            const int c = hd + m0w + di * 8 + 2 * tig;
            *(float2*)&g_attn[r * LH + c]       = make_float2(o[ni][di][0], o[ni][di][1]);
            *(float2*)&g_attn[(r + 8) * LH + c] = make_float2(o[ni][di][2], o[ni][di][3]);
        }
}

// ---------------- 4) output LN * u + residual ----------------
__global__ __launch_bounds__(256) void out_kernel(const float* __restrict__ ue,
                                                  const float* __restrict__ g,
                                                  const float* __restrict__ be,
                                                  float* __restrict__ out) {
    const int row = blockIdx.x, t = threadIdx.x;
    const float* ar = g_attn + (size_t)row * LH;
    float a0 = ar[t], a1 = ar[t + 256];
    float2 r = block_reduce_sum2(a0 + a1, a0 * a0 + a1 * a1);
    float mu = r.x * (1.f / 512.f);
    float var = r.y * (1.f / 512.f) - mu * mu;
    float rs = rsqrtf(var + 1e-6f);
    const float* ur  = g_proj + (size_t)row * FF + OFF_U;
    const float* uer = ue + (size_t)row * EE;
    float* orow = out + (size_t)row * EE;
    orow[t]       = uer[t]       + ((a0 - mu) * rs * g[t]       + be[t])       * ur[t];
    orow[t + 256] = uer[t + 256] + ((a1 - mu) * rs * g[t + 256] + be[t + 256]) * ur[t + 256];
}

extern "C" void kernel_launch(void* const* d_in, const int* in_sizes, int n_in,
                              void* d_out, int out_size) {
    (void)in_sizes; (void)n_in; (void)out_size;
    const float* ue   = (const float*)d_in[0];
    const float* uvqk = (const float*)d_in[2];
    const float* ing  = (const float*)d_in[3];
    const float* inb  = (const float*)d_in[4];
    const float* outg = (const float*)d_in[5];
    const float* outb = (const float*)d_in[6];
    float* out = (float*)d_out;

    cudaFuncSetAttribute(attn_kernel, cudaFuncAttributeMaxDynamicSharedMemorySize, ATTN_SMEM);

    ln_in_kernel<<<NROW, 256>>>(ue, ing, inb);
    gemm_proj_kernel<<<dim3(FF / 128, NROW / 128), 256>>>(uvqk);
    attn_kernel<<<dim3(SS / 64, BB * HH), 256, ATTN_SMEM>>>();
    out_kernel<<<NROW, 256>>>(ue, outg, outb, out);
}